// round 13
// baseline (speedup 1.0000x reference)
#include <cuda_runtime.h>
#include <cuda_fp16.h>
#include <cstdint>

#define VOCAB 30000
#define TT    512
#define HH    100
#define EE    32
#define BB    32
#define NBLK  128
#define NTH   416

// ---- SMEM byte offsets ----
#define SM_TOKS 0        // [2][32] int
#define SM_LTOK 256      // [32] int
#define SM_FLAG 384
#define SM_W    512      // 400 rows x 240 B fp16 (W, row n = gate*100+j, k-major)
#define SM_AH   96512    // 32 rows x 240 B fp16 (h hi)
#define SM_AL   104192   // 32 rows x 240 B fp16 (h lo)
#define SM_GS   111872   // 400 x 33 f32 staging (D^T: rows = gate outputs, cols = batch)
#define SM_END  164672
#define GSTR    33       // stride 33: conflict-free epilogue column reads

__device__ float g_xpre[(size_t)VOCAB * HH * 4];   // [v][j][f,i,o,g], exact fp32 x-part

__device__ __forceinline__ float fsigm_x(float z){ return __fdividef(1.f, 1.f + __expf(-z)); }
__device__ __forceinline__ float ftanh_hw(float z){
    float r; asm("tanh.approx.f32 %0, %1;" : "=f"(r) : "f"(z)); return r;
}
__device__ __forceinline__ float fsigm_hw(float z){
    return fmaf(ftanh_hw(0.5f * z), 0.5f, 0.5f);
}
__device__ __forceinline__ uint32_t smem_u32(const void* p){
    uint32_t a; asm("{ .reg .u64 t; cvta.to.shared.u64 t, %1; cvt.u32.u64 %0, t; }" : "=r"(a) : "l"(p)); return a;
}
__device__ __forceinline__ void ldsm_x4(uint32_t& r0, uint32_t& r1, uint32_t& r2, uint32_t& r3, uint32_t a){
    asm volatile("ldmatrix.sync.aligned.m8n8.x4.shared.b16 {%0,%1,%2,%3}, [%4];"
                 : "=r"(r0), "=r"(r1), "=r"(r2), "=r"(r3) : "r"(a));
}
__device__ __forceinline__ void mma16816(float* c, const uint32_t* a, uint32_t b0, uint32_t b1){
    asm volatile("mma.sync.aligned.m16n8k16.row.col.f32.f16.f16.f32 "
                 "{%0,%1,%2,%3}, {%4,%5,%6,%7}, {%8,%9}, {%0,%1,%2,%3};"
                 : "+f"(c[0]), "+f"(c[1]), "+f"(c[2]), "+f"(c[3])
                 : "r"(a[0]), "r"(a[1]), "r"(a[2]), "r"(a[3]), "r"(b0), "r"(b1));
}

// ---------------------------------------------------------------------------
__global__ void xpre_kernel(const float* __restrict__ emb,
                            const float* __restrict__ Wf, const float* __restrict__ bf,
                            const float* __restrict__ Wi, const float* __restrict__ bi,
                            const float* __restrict__ Wo, const float* __restrict__ bo,
                            const float* __restrict__ Wc, const float* __restrict__ bc) {
    int v = blockIdx.x;
    __shared__ float e[EE];
    if (threadIdx.x < EE) e[threadIdx.x] = emb[v * EE + threadIdx.x];
    __syncthreads();
    for (int n = threadIdx.x; n < HH * 4; n += blockDim.x) {
        int j = n >> 2, gate = n & 3;
        const float* W = (gate==0)?Wf:(gate==1)?Wi:(gate==2)?Wo:Wc;
        const float* b = (gate==0)?bf:(gate==1)?bi:(gate==2)?bo:bc;
        float s = b[j];
#pragma unroll
        for (int k = 0; k < EE; k++) s = fmaf(e[k], W[k*HH+j], s);
        g_xpre[((size_t)v*HH + j)*4 + gate] = s;
    }
}

// ---------------------------------------------------------------------------
// Persistent HMMA LSTM, W-in-registers: D^T[400,32] = W(A, regs) @ h^T(B, smem).
// 13 warps: wid<12 own 2 m16-tiles (32 gate-outputs), wid 12 owns 1.
// A(W) fragments loaded ONCE before the time loop. Per step: 28 ldsm_x4 (h
// hi/lo) + 112 MMA per warp; epilogue 400 threads with HW tanh.
// ---------------------------------------------------------------------------
__global__ void __launch_bounds__(NTH, 1)
lstm_kernel(const int* __restrict__ data32,
            const float* __restrict__ Wf, const float* __restrict__ Wi,
            const float* __restrict__ Wo4, const float* __restrict__ Wc,
            const float* __restrict__ WoOut, const float* __restrict__ boOut,
            float* __restrict__ out) {
    extern __shared__ char smem[];
    const uint32_t sbase = smem_u32(smem);
    const int tid = threadIdx.x, wid = tid >> 5, lane = tid & 31;
    const int b0 = blockIdx.x * BB;

    int*    toks = (int*)(smem + SM_TOKS);
    int*    ltok = (int*)(smem + SM_LTOK);
    int*    flag = (int*)(smem + SM_FLAG);
    float*  gs   = (float*)(smem + SM_GS);
    __half* ah   = (__half*)(smem + SM_AH);
    __half* al   = (__half*)(smem + SM_AL);

    if (tid == 0) {
        int is64 = 1;
        for (int i = 0; i < 64; i++) if (data32[2*i+1] != 0) { is64 = 0; break; }
        flag[0] = is64;
    }
    // zero W (incl k padding) + h staging
    for (int idx = tid*4; idx < SM_GS - SM_W; idx += NTH*4)
        *(uint32_t*)(smem + SM_W + idx) = 0u;
    __syncthreads();
    // fill W fp16: row n = gate*100+j, col k -> Wg[(32+k)*100+j]
    for (int idx = tid; idx < 400 * HH; idx += NTH) {
        int n = idx / HH, k = idx % HH, gate = n / HH, j = n % HH;
        const float* W = (gate==0)?Wf:(gate==1)?Wi:(gate==2)?Wo4:Wc;
        *(__half*)(smem + SM_W + n*240 + k*2) = __float2half_rn(W[(EE+k)*HH + j]);
    }
    const int is64 = flag[0];
    if (tid < BB) {
        long long base = (long long)(b0 + tid) * TT;
        ltok[tid] = is64 ? data32[2*(base+TT-1)] : data32[base+TT-1];
        toks[tid] = is64 ? data32[2*base]        : data32[base];
    }
    __syncthreads();

    // ---- load A (W) fragments into registers, once ----
    const int two = (wid < 12);           // uniform per warp
    const int m0  = wid * 32;
    uint32_t aW[56];
#pragma unroll
    for (int mt = 0; mt < 2; mt++) {
        if (mt == 1 && !two) break;
        uint32_t aAddr = sbase + SM_W + (uint32_t)(m0 + mt*16 + (lane & 15)) * 240u
                       + (uint32_t)(lane >> 4) * 16u;
#pragma unroll
        for (int kc = 0; kc < 7; kc++)
            ldsm_x4(aW[mt*28+kc*4], aW[mt*28+kc*4+1], aW[mt*28+kc*4+2], aW[mt*28+kc*4+3],
                    aAddr + kc*32);
    }

    // B (h) lane addressing: matrices (b0-7,k0),(b0-7,k8),(b8-15,k0),(b8-15,k8)
    const uint32_t mtx  = lane >> 3;
    const uint32_t bOff = (((mtx >> 1) * 8) + (lane & 7)) * 240u + (mtx & 1) * 16u;

    const int bg = (tid < 400) ? tid / 100 : 0;
    const int j  = (tid < 400) ? tid % 100 : 0;
    float c[8];
#pragma unroll
    for (int i = 0; i < 8; i++) c[i] = 0.f;

    int cur = 0;
    for (int t = 0; t < TT - 1; ++t) {
        __syncthreads();   // B1: h hi/lo staging + toks[cur] ready

        // ---- MMA: D^T = W @ h^T (hi + lo terms share A regs & B loads per term) ----
        float acc[2][4][4];
#pragma unroll
        for (int mt = 0; mt < 2; mt++)
#pragma unroll
            for (int nt = 0; nt < 4; nt++)
#pragma unroll
                for (int q = 0; q < 4; q++) acc[mt][nt][q] = 0.f;

        const uint32_t aH = sbase + SM_AH + bOff;
        const uint32_t aL = sbase + SM_AL + bOff;
#pragma unroll
        for (int kc = 0; kc < 7; kc++) {
            uint32_t p0,p1,p2,p3, q0,q1,q2,q3;
            // hi term
            ldsm_x4(p0,p1,p2,p3, aH + kc*32);
            ldsm_x4(q0,q1,q2,q3, aH + 16*240 + kc*32);
            mma16816(acc[0][0], aW + kc*4, p0,p1);
            mma16816(acc[0][1], aW + kc*4, p2,p3);
            mma16816(acc[0][2], aW + kc*4, q0,q1);
            mma16816(acc[0][3], aW + kc*4, q2,q3);
            if (two) {
                mma16816(acc[1][0], aW + 28 + kc*4, p0,p1);
                mma16816(acc[1][1], aW + 28 + kc*4, p2,p3);
                mma16816(acc[1][2], aW + 28 + kc*4, q0,q1);
                mma16816(acc[1][3], aW + 28 + kc*4, q2,q3);
            }
            // lo term
            ldsm_x4(p0,p1,p2,p3, aL + kc*32);
            ldsm_x4(q0,q1,q2,q3, aL + 16*240 + kc*32);
            mma16816(acc[0][0], aW + kc*4, p0,p1);
            mma16816(acc[0][1], aW + kc*4, p2,p3);
            mma16816(acc[0][2], aW + kc*4, q0,q1);
            mma16816(acc[0][3], aW + kc*4, q2,q3);
            if (two) {
                mma16816(acc[1][0], aW + 28 + kc*4, p0,p1);
                mma16816(acc[1][1], aW + 28 + kc*4, p2,p3);
                mma16816(acc[1][2], aW + 28 + kc*4, q0,q1);
                mma16816(acc[1][3], aW + 28 + kc*4, q2,q3);
            }
        }
        // store D^T frags: thread holds rows r0,r0+8 x cols (nt*8 + (lane&3)*2, +1)
        {
            int r0 = m0 + (lane >> 2), cl2 = (lane & 3) * 2;
#pragma unroll
            for (int mt = 0; mt < 2; mt++) {
                if (mt == 1 && !two) break;
                int rr = r0 + mt*16;
#pragma unroll
                for (int nt = 0; nt < 4; nt++) {
                    int n = nt*8 + cl2;
                    gs[rr*GSTR + n]       = acc[mt][nt][0];
                    gs[rr*GSTR + n + 1]   = acc[mt][nt][1];
                    gs[(rr+8)*GSTR + n]   = acc[mt][nt][2];
                    gs[(rr+8)*GSTR + n+1] = acc[mt][nt][3];
                }
            }
        }
        if (wid == 12) {   // prefetch next tokens
            long long base = (long long)(b0 + lane) * TT + (t + 1);
            toks[(cur ^ 1) * BB + lane] = is64 ? data32[2*base] : data32[base];
        }
        // xpre gathers (issued after MMA, overlap the B2 sync + others' tails)
        int tk[8]; float4 xp[8];
        if (tid < 400) {
#pragma unroll
            for (int i = 0; i < 8; i++) {
                tk[i] = toks[cur * BB + bg*8 + i];
                xp[i] = __ldg((const float4*)(g_xpre + ((size_t)tk[i]*HH + j)*4));
            }
        }
        __syncthreads();   // B2: gs ready

        if (tid < 400) {
#pragma unroll
            for (int i = 0; i < 8; i++) {
                int b = bg*8 + i;
                float f  = fsigm_hw(gs[(      j)*GSTR + b] + xp[i].x);
                float ii = fsigm_hw(gs[(100 + j)*GSTR + b] + xp[i].y);
                float o  = fsigm_hw(gs[(200 + j)*GSTR + b] + xp[i].z);
                float gg = ftanh_hw(gs[(300 + j)*GSTR + b] + xp[i].w);
                float cn = fmaf(c[i], f, ii * gg);
                if (tk[i] != ltok[b]) {
                    c[i] = cn;
                    float hv = o * ftanh_hw(cn);
                    __half hi = __float2half_rn(hv);
                    __half lo = __float2half_rn(hv - __half2float(hi));
                    ah[b*120 + j] = hi;
                    al[b*120 + j] = lo;
                }
            }
        }
        cur ^= 1;
    }

    // output head (exact fp32 sigmoid); reconstruct h = hi + lo from staging
    __syncthreads();
    if (tid < 400) {
#pragma unroll
        for (int i = 0; i < 8; i++) {
            int b = bg*8 + i;
            gs[b*104 + j] = __half2float(ah[b*120 + j]) + __half2float(al[b*120 + j]);
        }
    }
    __syncthreads();
    if (tid < BB) {
        float z = boOut[0];
#pragma unroll 4
        for (int k = 0; k < HH; k++) z = fmaf(gs[tid*104 + k], WoOut[k], z);
        out[b0 + tid] = fsigm_x(z);
    }
}

// ---------------------------------------------------------------------------
extern "C" void kernel_launch(void* const* d_in, const int* in_sizes, int n_in,
                              void* d_out, int out_size) {
    const int*   data = (const int*)  d_in[0];
    const float* emb  = (const float*)d_in[1];
    const float* Wfh  = (const float*)d_in[2];
    const float* bfh  = (const float*)d_in[3];
    const float* Wih  = (const float*)d_in[4];
    const float* bih  = (const float*)d_in[5];
    const float* Woh  = (const float*)d_in[6];
    const float* boh  = (const float*)d_in[7];
    const float* Wch  = (const float*)d_in[8];
    const float* bch  = (const float*)d_in[9];
    const float* Wo   = (const float*)d_in[10];
    const float* bo   = (const float*)d_in[11];
    float* out = (float*)d_out;

    xpre_kernel<<<VOCAB, 128>>>(emb, Wfh, bfh, Wih, bih, Woh, boh, Wch, bch);

    cudaFuncSetAttribute(lstm_kernel, cudaFuncAttributeMaxDynamicSharedMemorySize, SM_END);
    lstm_kernel<<<NBLK, NTH, SM_END>>>(data, Wfh, Wih, Woh, Wch, Wo, bo, out);
}

// round 14
// speedup vs baseline: 1.8369x; 1.8369x over previous
#include <cuda_runtime.h>
#include <cuda_fp16.h>
#include <cstdint>

#define VOCAB 30000
#define TT    512
#define HH    100
#define EE    32
#define BB    32
#define NBLK  128
#define NTH   416

// ---- SMEM byte offsets ----
#define SM_TOKS 0        // [2][32] int
#define SM_LTOK 256      // [32] int
#define SM_FLAG 384
#define SM_W    512      // 400 rows x 240 B fp16 (W^T, k-major, padded)
#define SM_AH   96512    // 32 rows x 240 B fp16 (h fp16)
#define SM_GS   104192   // 32 x 404 f32 staging
#define SM_END  155904
#define GSTR    404      // gs row stride (floats)

__device__ float g_xpre[(size_t)VOCAB * HH * 4];   // [v][j][f,i,o,g], exact fp32 x-part

// exact (used for xpre build + final output only)
__device__ __forceinline__ float fsigm_x(float z){ return __fdividef(1.f, 1.f + __expf(-z)); }
// HW tanh path (epilogue)
__device__ __forceinline__ float ftanh_hw(float z){
    float r; asm("tanh.approx.f32 %0, %1;" : "=f"(r) : "f"(z)); return r;
}
__device__ __forceinline__ float fsigm_hw(float z){
    return fmaf(ftanh_hw(0.5f * z), 0.5f, 0.5f);
}
__device__ __forceinline__ uint32_t smem_u32(const void* p){
    uint32_t a; asm("{ .reg .u64 t; cvta.to.shared.u64 t, %1; cvt.u32.u64 %0, t; }" : "=r"(a) : "l"(p)); return a;
}
__device__ __forceinline__ void ldsm_x4(uint32_t& r0, uint32_t& r1, uint32_t& r2, uint32_t& r3, uint32_t a){
    asm volatile("ldmatrix.sync.aligned.m8n8.x4.shared.b16 {%0,%1,%2,%3}, [%4];"
                 : "=r"(r0), "=r"(r1), "=r"(r2), "=r"(r3) : "r"(a));
}
__device__ __forceinline__ void ldsm_x2(uint32_t& r0, uint32_t& r1, uint32_t a){
    asm volatile("ldmatrix.sync.aligned.m8n8.x2.shared.b16 {%0,%1}, [%2];"
                 : "=r"(r0), "=r"(r1) : "r"(a));
}
__device__ __forceinline__ void mma16816(float* c, uint32_t a0, uint32_t a1, uint32_t a2, uint32_t a3,
                                         uint32_t b0, uint32_t b1){
    asm volatile("mma.sync.aligned.m16n8k16.row.col.f32.f16.f16.f32 "
                 "{%0,%1,%2,%3}, {%4,%5,%6,%7}, {%8,%9}, {%0,%1,%2,%3};"
                 : "+f"(c[0]), "+f"(c[1]), "+f"(c[2]), "+f"(c[3])
                 : "r"(a0), "r"(a1), "r"(a2), "r"(a3), "r"(b0), "r"(b1));
}

// ---------------------------------------------------------------------------
__global__ void xpre_kernel(const float* __restrict__ emb,
                            const float* __restrict__ Wf, const float* __restrict__ bf,
                            const float* __restrict__ Wi, const float* __restrict__ bi,
                            const float* __restrict__ Wo, const float* __restrict__ bo,
                            const float* __restrict__ Wc, const float* __restrict__ bc) {
    int v = blockIdx.x;
    __shared__ float e[EE];
    if (threadIdx.x < EE) e[threadIdx.x] = emb[v * EE + threadIdx.x];
    __syncthreads();
    for (int n = threadIdx.x; n < HH * 4; n += blockDim.x) {
        int j = n >> 2, gate = n & 3;
        const float* W = (gate==0)?Wf:(gate==1)?Wi:(gate==2)?Wo:Wc;
        const float* b = (gate==0)?bf:(gate==1)?bi:(gate==2)?bo:bc;
        float s = b[j];
#pragma unroll
        for (int k = 0; k < EE; k++) s = fmaf(e[k], W[k*HH+j], s);
        g_xpre[((size_t)v*HH + j)*4 + gate] = s;
    }
}

// ---------------------------------------------------------------------------
// Persistent HMMA LSTM: CTA = 32 batches, 511 steps.
// Warps 0-9: D[32,400] = h(fp16) @ W^T(fp16), fp32 accum. Single A term
// (h plain fp16 — W-fp16 already sets the error scale). Epilogue: 400
// threads, HW tanh. Two barriers/step.
// ---------------------------------------------------------------------------
__global__ void __launch_bounds__(NTH, 1)
lstm_kernel(const int* __restrict__ data32,
            const float* __restrict__ Wf, const float* __restrict__ Wi,
            const float* __restrict__ Wo4, const float* __restrict__ Wc,
            const float* __restrict__ WoOut, const float* __restrict__ boOut,
            float* __restrict__ out) {
    extern __shared__ char smem[];
    const uint32_t sbase = smem_u32(smem);
    const int tid = threadIdx.x, wid = tid >> 5, lane = tid & 31;
    const int b0 = blockIdx.x * BB;

    int*   toks = (int*)(smem + SM_TOKS);
    int*   ltok = (int*)(smem + SM_LTOK);
    int*   flag = (int*)(smem + SM_FLAG);
    float* gs   = (float*)(smem + SM_GS);

    if (tid == 0) {
        int is64 = 1;
        for (int i = 0; i < 64; i++) if (data32[2*i+1] != 0) { is64 = 0; break; }
        flag[0] = is64;
    }
    for (int idx = tid*4; idx < SM_GS - SM_W; idx += NTH*4)
        *(uint32_t*)(smem + SM_W + idx) = 0u;
    __syncthreads();
    for (int idx = tid; idx < 400 * HH; idx += NTH) {
        int n = idx / HH, k = idx % HH, gate = n / HH, j = n % HH;
        const float* W = (gate==0)?Wf:(gate==1)?Wi:(gate==2)?Wo4:Wc;
        *(__half*)(smem + SM_W + n*240 + k*2) = __float2half_rn(W[(EE+k)*HH + j]);
    }
    const int is64 = flag[0];
    if (tid < BB) {
        long long base = (long long)(b0 + tid) * TT;
        ltok[tid] = is64 ? data32[2*(base+TT-1)] : data32[base+TT-1];
        toks[tid] = is64 ? data32[2*base]        : data32[base];
    }
    __syncthreads();

    const int bg = (tid < 400) ? tid / 100 : 0;
    const int j  = (tid < 400) ? tid % 100 : 0;
    float c[8], hreg[8];
#pragma unroll
    for (int i = 0; i < 8; i++) { c[i] = 0.f; hreg[i] = 0.f; }

    const int m0  = (wid < 5) ? 0 : 16;
    const int nt0 = (wid % 5) * 10;
    const uint32_t aOff = (uint32_t)(m0 + (lane & 15)) * 240u + (uint32_t)(lane >> 4) * 16u;
    const uint32_t bAdr = sbase + SM_W + (uint32_t)(nt0*8 + (lane & 7)) * 240u
                        + (uint32_t)((lane >> 3) & 1) * 16u;

    int cur = 0;
    for (int t = 0; t < TT - 1; ++t) {
        __syncthreads();   // B1: h staging + toks[cur] ready

        int tk[8]; float4 xp[8];
        if (tid < 400) {
#pragma unroll
            for (int i = 0; i < 8; i++) {
                tk[i] = toks[cur * BB + bg*8 + i];
                xp[i] = __ldg((const float4*)(g_xpre + ((size_t)tk[i]*HH + j)*4));
            }
        }
        if (wid == 12 && lane < BB) {
            long long base = (long long)(b0 + lane) * TT + (t + 1);
            toks[(cur ^ 1) * BB + lane] = is64 ? data32[2*base] : data32[base];
        }

        if (wid < 10) {
            float acc[10][4];
#pragma unroll
            for (int i = 0; i < 10; i++) { acc[i][0]=0.f; acc[i][1]=0.f; acc[i][2]=0.f; acc[i][3]=0.f; }
            uint32_t aH = sbase + SM_AH + aOff;
#pragma unroll
            for (int kc = 0; kc < 7; kc++) {
                uint32_t h0,h1,h2,h3;
                ldsm_x4(h0,h1,h2,h3, aH + kc*32);
#pragma unroll
                for (int i = 0; i < 10; i++) {
                    uint32_t b0r,b1r;
                    ldsm_x2(b0r,b1r, bAdr + i*(8*240) + kc*32);
                    mma16816(acc[i], h0,h1,h2,h3, b0r,b1r);
                }
            }
            int r0 = m0 + (lane >> 2), cl = (lane & 3) * 2;
#pragma unroll
            for (int i = 0; i < 10; i++) {
                int n = (nt0 + i)*8 + cl;
                *(float2*)(gs + r0*GSTR + n)     = make_float2(acc[i][0], acc[i][1]);
                *(float2*)(gs + (r0+8)*GSTR + n) = make_float2(acc[i][2], acc[i][3]);
            }
        }
        __syncthreads();   // B2: gs ready

        if (tid < 400) {
#pragma unroll
            for (int i = 0; i < 8; i++) {
                int b = bg*8 + i;
                float f  = fsigm_hw(gs[b*GSTR +       j] + xp[i].x);
                float ii = fsigm_hw(gs[b*GSTR + 100 + j] + xp[i].y);
                float o  = fsigm_hw(gs[b*GSTR + 200 + j] + xp[i].z);
                float gg = ftanh_hw(gs[b*GSTR + 300 + j] + xp[i].w);
                float cn = fmaf(c[i], f, ii * gg);
                bool  m  = (tk[i] != ltok[b]);
                c[i]    = m ? cn : c[i];
                hreg[i] = m ? o * ftanh_hw(cn) : hreg[i];
                *(__half*)(smem + SM_AH + b*240 + j*2) = __float2half_rn(hreg[i]);
            }
        }
        cur ^= 1;
    }

    // output head (exact fp32 sigmoid, fp32 h from registers)
    __syncthreads();
    if (tid < 400) {
#pragma unroll
        for (int i = 0; i < 8; i++) gs[(bg*8 + i)*104 + j] = hreg[i];
    }
    __syncthreads();
    if (tid < BB) {
        float z = boOut[0];
#pragma unroll 4
        for (int k = 0; k < HH; k++) z = fmaf(gs[tid*104 + k], WoOut[k], z);
        out[b0 + tid] = fsigm_x(z);
    }
}

// ---------------------------------------------------------------------------
extern "C" void kernel_launch(void* const* d_in, const int* in_sizes, int n_in,
                              void* d_out, int out_size) {
    const int*   data = (const int*)  d_in[0];
    const float* emb  = (const float*)d_in[1];
    const float* Wfh  = (const float*)d_in[2];
    const float* bfh  = (const float*)d_in[3];
    const float* Wih  = (const float*)d_in[4];
    const float* bih  = (const float*)d_in[5];
    const float* Woh  = (const float*)d_in[6];
    const float* boh  = (const float*)d_in[7];
    const float* Wch  = (const float*)d_in[8];
    const float* bch  = (const float*)d_in[9];
    const float* Wo   = (const float*)d_in[10];
    const float* bo   = (const float*)d_in[11];
    float* out = (float*)d_out;

    xpre_kernel<<<VOCAB, 128>>>(emb, Wfh, bfh, Wih, bih, Woh, boh, Wch, bch);

    cudaFuncSetAttribute(lstm_kernel, cudaFuncAttributeMaxDynamicSharedMemorySize, SM_END);
    lstm_kernel<<<NBLK, NTH, SM_END>>>(data, Wfh, Wih, Woh, Wch, Wo, bo, out);
}

// round 15
// speedup vs baseline: 1.9817x; 1.0788x over previous
#include <cuda_runtime.h>
#include <cuda_fp16.h>
#include <cstdint>

#define VOCAB 30000
#define TT    512
#define HH    100
#define EE    32
#define BB    32
#define NBLK  128
#define NTH   832          // 26 warps: 13 MMA + 13 epilogue
#define CNT   832

// ---- SMEM byte offsets ----
#define SM_FLAG 0
#define SM_W    128        // 416 rows x 240 B fp16 (W^T padded, k-major)
#define SM_HA   99968      // 16 rows x 240 B fp16 (h group A)
#define SM_HB   103808     // 16 rows x 240 B fp16 (h group B)
#define SM_GA   107648     // 16 x 424 f32 gates, group A
#define SM_GB   134784     // 16 x 424 f32 gates, group B
#define SM_END  161920
#define GSTR    424

__device__ float g_xpre[(size_t)VOCAB * HH * 4];   // [v][j][f,i,o,g], exact fp32 x-part

__device__ __forceinline__ float fsigm_x(float z){ return __fdividef(1.f, 1.f + __expf(-z)); }
__device__ __forceinline__ float ftanh_hw(float z){
    float r; asm("tanh.approx.f32 %0, %1;" : "=f"(r) : "f"(z)); return r;
}
__device__ __forceinline__ float fsigm_hw(float z){
    return fmaf(ftanh_hw(0.5f * z), 0.5f, 0.5f);
}
__device__ __forceinline__ uint32_t smem_u32(const void* p){
    uint32_t a; asm("{ .reg .u64 t; cvta.to.shared.u64 t, %1; cvt.u32.u64 %0, t; }" : "=r"(a) : "l"(p)); return a;
}
__device__ __forceinline__ void ldsm_x4(uint32_t& r0, uint32_t& r1, uint32_t& r2, uint32_t& r3, uint32_t a){
    asm volatile("ldmatrix.sync.aligned.m8n8.x4.shared.b16 {%0,%1,%2,%3}, [%4];"
                 : "=r"(r0), "=r"(r1), "=r"(r2), "=r"(r3) : "r"(a));
}
__device__ __forceinline__ void mma16816(float* c, uint32_t a0, uint32_t a1, uint32_t a2, uint32_t a3,
                                         uint32_t b0, uint32_t b1){
    asm volatile("mma.sync.aligned.m16n8k16.row.col.f32.f16.f16.f32 "
                 "{%0,%1,%2,%3}, {%4,%5,%6,%7}, {%8,%9}, {%0,%1,%2,%3};"
                 : "+f"(c[0]), "+f"(c[1]), "+f"(c[2]), "+f"(c[3])
                 : "r"(a0), "r"(a1), "r"(a2), "r"(a3), "r"(b0), "r"(b1));
}
#define BSYNC(id)   asm volatile("bar.sync %0, %1;"   :: "r"(id), "r"(CNT) : "memory")
#define BARRIVE(id) asm volatile("bar.arrive %0, %1;" :: "r"(id), "r"(CNT) : "memory")

// ---------------------------------------------------------------------------
__global__ void xpre_kernel(const float* __restrict__ emb,
                            const float* __restrict__ Wf, const float* __restrict__ bf,
                            const float* __restrict__ Wi, const float* __restrict__ bi,
                            const float* __restrict__ Wo, const float* __restrict__ bo,
                            const float* __restrict__ Wc, const float* __restrict__ bc) {
    int v = blockIdx.x;
    __shared__ float e[EE];
    if (threadIdx.x < EE) e[threadIdx.x] = emb[v * EE + threadIdx.x];
    __syncthreads();
    for (int n = threadIdx.x; n < HH * 4; n += blockDim.x) {
        int j = n >> 2, gate = n & 3;
        const float* W = (gate==0)?Wf:(gate==1)?Wi:(gate==2)?Wo:Wc;
        const float* b = (gate==0)?bf:(gate==1)?bi:(gate==2)?bo:bc;
        float s = b[j];
#pragma unroll
        for (int k = 0; k < EE; k++) s = fmaf(e[k], W[k*HH+j], s);
        g_xpre[((size_t)v*HH + j)*4 + gate] = s;
    }
}

// ---------------------------------------------------------------------------
// Two-stream pipelined HMMA LSTM. 32 batches = 2 independent groups of 16.
// Warps 0-12: MMA (D_g[16,416] = h_g fp16 @ W^T fp16, 4 n8-tiles/warp).
// Warps 13-25: epilogue (activations, c/h update, token+xpre prefetch).
// Named barriers: 1=hA ready, 2=gsA ready, 3=hB ready, 4=gsB ready.
// While MMA does group B, epilogue processes group A (and vice versa).
// ---------------------------------------------------------------------------
__global__ void __launch_bounds__(NTH, 1)
lstm_kernel(const int* __restrict__ data32,
            const float* __restrict__ Wf, const float* __restrict__ Wi,
            const float* __restrict__ Wo4, const float* __restrict__ Wc,
            const float* __restrict__ WoOut, const float* __restrict__ boOut,
            float* __restrict__ out) {
    extern __shared__ char smem[];
    const uint32_t sbase = smem_u32(smem);
    const int tid = threadIdx.x, wid = tid >> 5, lane = tid & 31;
    const int b0 = blockIdx.x * BB;
    int* flag = (int*)(smem + SM_FLAG);

    if (tid == 0) {
        int is64d = 1;
        for (int i = 0; i < 64; i++) if (data32[2*i+1] != 0) { is64d = 0; break; }
        flag[0] = is64d;
    }
    // zero W (incl padding rows/cols) + both h stagings
    for (int idx = tid*4; idx < SM_GA - SM_W; idx += NTH*4)
        *(uint32_t*)(smem + SM_W + idx) = 0u;
    __syncthreads();
    // fill W^T fp16: row n = gate*100+j, col k -> Wg[(32+k)*100+j]
    for (int idx = tid; idx < 400 * HH; idx += NTH) {
        int n = idx / HH, k = idx % HH, gate = n / HH, j = n % HH;
        const float* W = (gate==0)?Wf:(gate==1)?Wi:(gate==2)?Wo4:Wc;
        *(__half*)(smem + SM_W + n*240 + k*2) = __float2half_rn(W[(EE+k)*HH + j]);
    }
    __syncthreads();
    const int is64 = flag[0];

    if (wid < 13) {
        // ================= MMA warps =================
        const int w = wid;
        const uint32_t aOff  = (uint32_t)(lane & 15) * 240u + (uint32_t)(lane >> 4) * 16u;
        const uint32_t bHalf = (uint32_t)((lane >> 3) & 1) * 16u;
        const uint32_t bRow0 = (uint32_t)((4*w + (lane >> 4)) * 8 + (lane & 7));
        const uint32_t bAdr0 = sbase + SM_W + bRow0 * 240u + bHalf;
        const uint32_t bAdr1 = bAdr0 + 16u * 240u;
        const int r0 = lane >> 2, cl = (lane & 3) * 2;

        for (int t = 0; t < TT - 1; ++t) {
#pragma unroll
            for (int g = 0; g < 2; ++g) {
                BSYNC(1 + 2*g);                          // wait h_g staged
                float acc[4][4];
#pragma unroll
                for (int ti = 0; ti < 4; ti++)
#pragma unroll
                    for (int q = 0; q < 4; q++) acc[ti][q] = 0.f;
                uint32_t aAdr = sbase + (g ? SM_HB : SM_HA) + aOff;
#pragma unroll
                for (int kc = 0; kc < 7; kc++) {
                    uint32_t a0,a1,a2,a3, c0,c1,c2,c3, d0,d1,d2,d3;
                    ldsm_x4(a0,a1,a2,a3, aAdr + kc*32);
                    ldsm_x4(c0,c1,c2,c3, bAdr0 + kc*32);
                    ldsm_x4(d0,d1,d2,d3, bAdr1 + kc*32);
                    mma16816(acc[0], a0,a1,a2,a3, c0,c1);
                    mma16816(acc[1], a0,a1,a2,a3, c2,c3);
                    mma16816(acc[2], a0,a1,a2,a3, d0,d1);
                    mma16816(acc[3], a0,a1,a2,a3, d2,d3);
                }
                float* gsg = (float*)(smem + (g ? SM_GB : SM_GA));
#pragma unroll
                for (int ti = 0; ti < 4; ti++) {
                    int n = (4*w + ti)*8 + cl;
                    *(float2*)(gsg + r0*GSTR + n)     = make_float2(acc[ti][0], acc[ti][1]);
                    *(float2*)(gsg + (r0+8)*GSTR + n) = make_float2(acc[ti][2], acc[ti][3]);
                }
                BARRIVE(2 + 2*g);                        // gs_g ready
            }
        }
    } else {
        // ================= epilogue warps =================
        const int e   = tid - 416;
        const bool act = (e < 400);
        const int j = e % 100, q = e / 100;
        float  c[2][4];
        int    lt[2][4], tk[2][4];
        float4 xp[2][4];
        if (act) {
#pragma unroll
            for (int g = 0; g < 2; g++)
#pragma unroll
                for (int i = 0; i < 4; i++) {
                    long long gb = (long long)(b0 + g*16 + q*4 + i) * TT;
                    lt[g][i] = is64 ? data32[2*(gb + TT-1)] : data32[gb + TT-1];
                    tk[g][i] = is64 ? data32[2*gb]          : data32[gb];
                    xp[g][i] = __ldg((const float4*)(g_xpre + ((size_t)tk[g][i]*HH + j)*4));
                    c[g][i]  = 0.f;
                }
        }
        BARRIVE(1); BARRIVE(3);                          // prime: h=0 already staged

        for (int t = 0; t < TT - 1; ++t) {
#pragma unroll
            for (int g = 0; g < 2; ++g) {
                BSYNC(2 + 2*g);                          // wait gs_g
                if (act) {
                    int tkn[4];
#pragma unroll
                    for (int i = 0; i < 4; i++) {        // issue next-step token loads
                        long long gb = (long long)(b0 + g*16 + q*4 + i) * TT + (t + 1);
                        tkn[i] = is64 ? data32[2*gb] : data32[gb];
                    }
                    const float* gsg = (const float*)(smem + (g ? SM_GB : SM_GA));
                    __half* ahg = (__half*)(smem + (g ? SM_HB : SM_HA));
#pragma unroll
                    for (int i = 0; i < 4; i++) {
                        int bl = q*4 + i;
                        float f  = fsigm_hw(gsg[bl*GSTR +       j] + xp[g][i].x);
                        float ii = fsigm_hw(gsg[bl*GSTR + 100 + j] + xp[g][i].y);
                        float o  = fsigm_hw(gsg[bl*GSTR + 200 + j] + xp[g][i].z);
                        float gg = ftanh_hw(gsg[bl*GSTR + 300 + j] + xp[g][i].w);
                        float cn = fmaf(c[g][i], f, ii * gg);
                        if (tk[g][i] != lt[g][i]) {
                            c[g][i] = cn;
                            ahg[bl*120 + j] = __float2half_rn(o * ftanh_hw(cn));
                        }
                    }
#pragma unroll
                    for (int i = 0; i < 4; i++) {        // prefetch next xpre rows
                        xp[g][i] = __ldg((const float4*)(g_xpre + ((size_t)tkn[i]*HH + j)*4));
                        tk[g][i] = tkn[i];
                    }
                }
                BARRIVE(1 + 2*g);                        // h_g staged for next step
            }
        }
    }

    __syncthreads();
    // output head: out[b] = sigmoid(h . Wo + bo), h from fp16 staging
    if (tid < BB) {
        const __half* hb = (const __half*)(smem + (tid < 16 ? SM_HA : SM_HB));
        int bl = tid & 15;
        float z = boOut[0];
#pragma unroll 4
        for (int k = 0; k < HH; k++)
            z = fmaf(__half2float(hb[bl*120 + k]), WoOut[k], z);
        out[b0 + tid] = fsigm_x(z);
    }
}

// ---------------------------------------------------------------------------
extern "C" void kernel_launch(void* const* d_in, const int* in_sizes, int n_in,
                              void* d_out, int out_size) {
    const int*   data = (const int*)  d_in[0];
    const float* emb  = (const float*)d_in[1];
    const float* Wfh  = (const float*)d_in[2];
    const float* bfh  = (const float*)d_in[3];
    const float* Wih  = (const float*)d_in[4];
    const float* bih  = (const float*)d_in[5];
    const float* Woh  = (const float*)d_in[6];
    const float* boh  = (const float*)d_in[7];
    const float* Wch  = (const float*)d_in[8];
    const float* bch  = (const float*)d_in[9];
    const float* Wo   = (const float*)d_in[10];
    const float* bo   = (const float*)d_in[11];
    float* out = (float*)d_out;

    xpre_kernel<<<VOCAB, 128>>>(emb, Wfh, bfh, Wih, bih, Woh, boh, Wch, bch);

    cudaFuncSetAttribute(lstm_kernel, cudaFuncAttributeMaxDynamicSharedMemorySize, SM_END);
    lstm_kernel<<<NBLK, NTH, SM_END>>>(data, Wfh, Wih, Woh, Wch, Wo, bo, out);
}

// round 16
// speedup vs baseline: 2.0147x; 1.0167x over previous
#include <cuda_runtime.h>
#include <cuda_fp16.h>
#include <cstdint>

#define VOCAB 30000
#define TT    512
#define HH    100
#define EE    32
#define BB    32
#define NBLK  128
#define NTH   416

// ---- SMEM byte offsets ----
#define SM_FLAG 0
#define SM_W    128        // 416 rows x 240 B fp16, row n = 4*j + gate, k-major
#define SM_H0   99968      // 32 x 240 B fp16 h buffer (even steps read)
#define SM_H1   107648     // odd steps read
#define SM_END  115456

__device__ float g_xpre[(size_t)VOCAB * HH * 4];   // [v][j][f,i,o,g], exact fp32 x-part

__device__ __forceinline__ float fsigm_x(float z){ return __fdividef(1.f, 1.f + __expf(-z)); }
__device__ __forceinline__ float ftanh_hw(float z){
    float r; asm("tanh.approx.f32 %0, %1;" : "=f"(r) : "f"(z)); return r;
}
__device__ __forceinline__ float fsigm_hw(float z){
    return fmaf(ftanh_hw(0.5f * z), 0.5f, 0.5f);
}
__device__ __forceinline__ uint32_t smem_u32(const void* p){
    uint32_t a; asm("{ .reg .u64 t; cvta.to.shared.u64 t, %1; cvt.u32.u64 %0, t; }" : "=r"(a) : "l"(p)); return a;
}
__device__ __forceinline__ void ldsm_x4(uint32_t& r0, uint32_t& r1, uint32_t& r2, uint32_t& r3, uint32_t a){
    asm volatile("ldmatrix.sync.aligned.m8n8.x4.shared.b16 {%0,%1,%2,%3}, [%4];"
                 : "=r"(r0), "=r"(r1), "=r"(r2), "=r"(r3) : "r"(a));
}
__device__ __forceinline__ void mma16816(float* c, uint32_t a0, uint32_t a1, uint32_t a2, uint32_t a3,
                                         uint32_t b0, uint32_t b1){
    asm volatile("mma.sync.aligned.m16n8k16.row.col.f32.f16.f16.f32 "
                 "{%0,%1,%2,%3}, {%4,%5,%6,%7}, {%8,%9}, {%0,%1,%2,%3};"
                 : "+f"(c[0]), "+f"(c[1]), "+f"(c[2]), "+f"(c[3])
                 : "r"(a0), "r"(a1), "r"(a2), "r"(a3), "r"(b0), "r"(b1));
}

// ---------------------------------------------------------------------------
__global__ void xpre_kernel(const float* __restrict__ emb,
                            const float* __restrict__ Wf, const float* __restrict__ bf,
                            const float* __restrict__ Wi, const float* __restrict__ bi,
                            const float* __restrict__ Wo, const float* __restrict__ bo,
                            const float* __restrict__ Wc, const float* __restrict__ bc) {
    int v = blockIdx.x;
    __shared__ float e[EE];
    if (threadIdx.x < EE) e[threadIdx.x] = emb[v * EE + threadIdx.x];
    __syncthreads();
    for (int n = threadIdx.x; n < HH * 4; n += blockDim.x) {
        int j = n >> 2, gate = n & 3;
        const float* W = (gate==0)?Wf:(gate==1)?Wi:(gate==2)?Wo:Wc;
        const float* b = (gate==0)?bf:(gate==1)?bi:(gate==2)?bo:bc;
        float s = b[j];
#pragma unroll
        for (int k = 0; k < EE; k++) s = fmaf(e[k], W[k*HH+j], s);
        g_xpre[((size_t)v*HH + j)*4 + gate] = s;
    }
}

// ---------------------------------------------------------------------------
// Fused HMMA LSTM: gate-interleaved W (n = 4j+gate) so each thread's output
// columns form gate pairs of one j; one shfl.bfly(1) completes the gate set
// and the LSTM cell update runs IN the MMA warps' registers. One barrier
// per step; h double-buffered in SMEM; tokens+xpre prefetched a step ahead.
// ---------------------------------------------------------------------------
__global__ void __launch_bounds__(NTH, 1)
lstm_kernel(const int* __restrict__ data32,
            const float* __restrict__ Wf, const float* __restrict__ Wi,
            const float* __restrict__ Wo4, const float* __restrict__ Wc,
            const float* __restrict__ WoOut, const float* __restrict__ boOut,
            float* __restrict__ out) {
    extern __shared__ char smem[];
    const uint32_t sbase = smem_u32(smem);
    const int tid = threadIdx.x, wid = tid >> 5, lane = tid & 31;
    const int b0 = blockIdx.x * BB;
    int* flag = (int*)(smem + SM_FLAG);

    if (tid == 0) {
        int is64d = 1;
        for (int i = 0; i < 64; i++) if (data32[2*i+1] != 0) { is64d = 0; break; }
        flag[0] = is64d;
    }
    // zero W (padding) + both h buffers
    for (int idx = tid*4; idx < SM_END - SM_W; idx += NTH*4)
        *(uint32_t*)(smem + SM_W + idx) = 0u;
    __syncthreads();
    // fill W fp16: row n = 4*j + gate, col k -> Wg[(32+k)*100 + j]
    for (int idx = tid; idx < 400 * HH; idx += NTH) {
        int n = idx / HH, k = idx % HH, j = n >> 2, gate = n & 3;
        const float* W = (gate==0)?Wf:(gate==1)?Wi:(gate==2)?Wo4:Wc;
        *(__half*)(smem + SM_W + n*240 + k*2) = __float2half_rn(W[(EE+k)*HH + j]);
    }
    __syncthreads();
    const int is64 = flag[0];

    // ---- per-thread geometry ----
    const uint32_t aOff  = (uint32_t)(lane & 15) * 240u + (uint32_t)(lane >> 4) * 16u;
    const uint32_t bAdr0 = sbase + SM_W
                         + (uint32_t)((4*wid + (lane >> 4)) * 8 + (lane & 7)) * 240u
                         + (uint32_t)((lane >> 3) & 1) * 16u;
    const uint32_t bAdr1 = bAdr0 + 16u * 240u;
    const bool qe = !(lane & 1);
    int bloc[2];
#pragma unroll
    for (int mt = 0; mt < 2; mt++) bloc[mt] = mt*16 + (lane >> 2) + (lane & 1)*8;

    // ---- state + prefetch for t=0 ----
    float c[2][4], hreg[2][4];
    int   tk[2], lt[2];
    float4 xp[2][4];
#pragma unroll
    for (int mt = 0; mt < 2; mt++) {
        long long gb = (long long)(b0 + bloc[mt]) * TT;
        lt[mt] = is64 ? data32[2*(gb + TT-1)] : data32[gb + TT-1];
        tk[mt] = is64 ? data32[2*gb]          : data32[gb];
#pragma unroll
        for (int i = 0; i < 4; i++) {
            int jt = 8*wid + 2*i + ((lane >> 1) & 1);
            int js = (jt < HH) ? jt : 0;
            xp[mt][i] = __ldg((const float4*)(g_xpre + ((size_t)tk[mt]*HH + js)*4));
            c[mt][i] = 0.f; hreg[mt][i] = 0.f;
        }
    }

    for (int t = 0; t < TT - 1; ++t) {
        __syncthreads();                       // h read-buffer ready for all warps
        const uint32_t hRd = sbase + ((t & 1) ? SM_H1 : SM_H0);

        // ---- MMA: D[32,416] = h @ W^T ----
        float acc[2][4][4];
#pragma unroll
        for (int mt = 0; mt < 2; mt++)
#pragma unroll
            for (int i = 0; i < 4; i++)
#pragma unroll
                for (int q = 0; q < 4; q++) acc[mt][i][q] = 0.f;
#pragma unroll
        for (int kc = 0; kc < 7; kc++) {
            uint32_t a0,a1,a2,a3, e0,e1,e2,e3, f0,f1,f2,f3, g0,g1,g2,g3;
            ldsm_x4(a0,a1,a2,a3, hRd + aOff + kc*32);             // m-tile 0
            ldsm_x4(e0,e1,e2,e3, hRd + 16*240 + aOff + kc*32);    // m-tile 1
            ldsm_x4(f0,f1,f2,f3, bAdr0 + kc*32);                  // n-tiles 4w,4w+1
            ldsm_x4(g0,g1,g2,g3, bAdr1 + kc*32);                  // n-tiles 4w+2,4w+3
            mma16816(acc[0][0], a0,a1,a2,a3, f0,f1);
            mma16816(acc[0][1], a0,a1,a2,a3, f2,f3);
            mma16816(acc[0][2], a0,a1,a2,a3, g0,g1);
            mma16816(acc[0][3], a0,a1,a2,a3, g2,g3);
            mma16816(acc[1][0], e0,e1,e2,e3, f0,f1);
            mma16816(acc[1][1], e0,e1,e2,e3, f2,f3);
            mma16816(acc[1][2], e0,e1,e2,e3, g0,g1);
            mma16816(acc[1][3], e0,e1,e2,e3, g2,g3);
        }

        // ---- prefetch next tokens (latency hidden behind epilogue) ----
        int tkn[2];
#pragma unroll
        for (int mt = 0; mt < 2; mt++) {
            long long gb = (long long)(b0 + bloc[mt]) * TT + (t + 1);
            tkn[mt] = is64 ? data32[2*gb] : data32[gb];
        }

        // ---- fused epilogue: shfl gate-pair exchange + cell update ----
        __half* hb = (__half*)(smem + (((t + 1) & 1) ? SM_H1 : SM_H0));
#pragma unroll
        for (int mt = 0; mt < 2; mt++) {
            const bool msk = (tk[mt] != lt[mt]);
#pragma unroll
            for (int i = 0; i < 4; i++) {
                float p0 = __shfl_xor_sync(0xFFFFFFFFu, acc[mt][i][0], 1);
                float p1 = __shfl_xor_sync(0xFFFFFFFFu, acc[mt][i][1], 1);
                float p2 = __shfl_xor_sync(0xFFFFFFFFu, acc[mt][i][2], 1);
                float p3 = __shfl_xor_sync(0xFFFFFFFFu, acc[mt][i][3], 1);
                float fz = qe ? acc[mt][i][0] : p2;
                float iz = qe ? acc[mt][i][1] : p3;
                float oz = qe ? p0 : acc[mt][i][2];
                float gz = qe ? p1 : acc[mt][i][3];
                int jt = 8*wid + 2*i + ((lane >> 1) & 1);
                float4 x = xp[mt][i];
                float f  = fsigm_hw(fz + x.x);
                float iv = fsigm_hw(iz + x.y);
                float o  = fsigm_hw(oz + x.z);
                float g  = ftanh_hw(gz + x.w);
                float cn = fmaf(c[mt][i], f, iv * g);
                if (msk) { c[mt][i] = cn; hreg[mt][i] = o * ftanh_hw(cn); }
                if (jt < HH) hb[bloc[mt]*120 + jt] = __float2half_rn(hreg[mt][i]);
            }
        }

        // ---- gather xpre for t+1 (consumed after next sync+MMA) ----
#pragma unroll
        for (int mt = 0; mt < 2; mt++) {
#pragma unroll
            for (int i = 0; i < 4; i++) {
                int jt = 8*wid + 2*i + ((lane >> 1) & 1);
                int js = (jt < HH) ? jt : 0;
                xp[mt][i] = __ldg((const float4*)(g_xpre + ((size_t)tkn[mt]*HH + js)*4));
            }
            tk[mt] = tkn[mt];
        }
    }

    // ---- output head: h final in SM_H1 (TT-1 is odd) ----
    __syncthreads();
    if (tid < BB) {
        const __half* hb = (const __half*)(smem + SM_H1);
        float z = boOut[0];
#pragma unroll 4
        for (int k = 0; k < HH; k++)
            z = fmaf(__half2float(hb[tid*120 + k]), WoOut[k], z);
        out[b0 + tid] = fsigm_x(z);
    }
}

// ---------------------------------------------------------------------------
extern "C" void kernel_launch(void* const* d_in, const int* in_sizes, int n_in,
                              void* d_out, int out_size) {
    const int*   data = (const int*)  d_in[0];
    const float* emb  = (const float*)d_in[1];
    const float* Wfh  = (const float*)d_in[2];
    const float* bfh  = (const float*)d_in[3];
    const float* Wih  = (const float*)d_in[4];
    const float* bih  = (const float*)d_in[5];
    const float* Woh  = (const float*)d_in[6];
    const float* boh  = (const float*)d_in[7];
    const float* Wch  = (const float*)d_in[8];
    const float* bch  = (const float*)d_in[9];
    const float* Wo   = (const float*)d_in[10];
    const float* bo   = (const float*)d_in[11];
    float* out = (float*)d_out;

    xpre_kernel<<<VOCAB, 128>>>(emb, Wfh, bfh, Wih, bih, Woh, boh, Wch, bch);

    cudaFuncSetAttribute(lstm_kernel, cudaFuncAttributeMaxDynamicSharedMemorySize, SM_END);
    lstm_kernel<<<NBLK, NTH, SM_END>>>(data, Wfh, Wih, Woh, Wch, Wo, bo, out);
}